// round 14
// baseline (speedup 1.0000x reference)
#include <cuda_runtime.h>
#include <cuda.h>
#include <cstdint>

// BicycleModel: B=65536 vehicles, 256 steps, 4 output planes [B,256] f32.
// R14: attack DRAM write row-locality. Stores now cover FULL 128B rows:
//  - state: 32v x 32t x 4 planes (16KB) SW128 tiles, double-buffered,
//    filled over two 16-step phases, ONE 3D TMA store {32,32,4} per 2 chunks
//  - controls: 16t SW64 tiles, double-buffered, distance-2 (unchanged)
//  - 40KB smem -> 5 blocks/SM; 4 sequential jobs/block -> grid 512 <= 740
//    slots -> single wave
//  - wait_group.read 1 guards a buffer 4 chunks back (ample store overlap)

constexpr int BV  = 65536;
constexpr int NS  = 256;
constexpr int BLK = 32;
constexpr int JOBS = 4;
constexpr int NCH = 16 * JOBS;     // 64 chunks of 16 timesteps
constexpr int CT4 = 128;           // float4 per 32x16 f32 ctrl tile (2KB)
constexpr int SB4 = 1024;          // float4 per state buffer (4p x 32v x 8)

constexpr float DT        = 0.05f;
constexpr float MAX_STEER = 0.52359877559829887f;
constexpr float MAX_SPEED = 100.0f;
constexpr float INV_WB    = 1.0f / 2.7f;

__device__ __forceinline__ uint32_t s2u(const void* p) {
    uint32_t a;
    asm("{ .reg .u64 t; cvta.to.shared.u64 t, %1; cvt.u32.u64 %0, t; }"
        : "=r"(a) : "l"(p));
    return a;
}

__global__ __launch_bounds__(BLK)
void bicycle_kernel(const __grid_constant__ CUtensorMap ta,   // acc  [B,256]
                    const __grid_constant__ CUtensorMap ts,   // steer[B,256]
                    const __grid_constant__ CUtensorMap to,   // out  [4,B,256]
                    const float* __restrict__ sx,
                    const float* __restrict__ sy,
                    const float* __restrict__ syaw,
                    const float* __restrict__ ssp)
{
    // Pool (40KB): cA[2][128] | cS[2][128] | sT[2][4][256]
    // ctrl bufs at 2KB multiples (uniform SW64 phase); state bufs 16KB apart,
    // planes 4KB apart, region at 8KB (all (off>>7)&7 == 0 -> uniform SW128).
    __shared__ alignas(1024) float4 pool[2560];
    __shared__ alignas(8) unsigned long long mb[2];

    float4* cA = pool;                 // [2][128]
    float4* cS = pool + 2 * CT4;       // [2][128]
    float4* sT = pool + 4 * CT4;       // [2][4][256]

    const int lane = threadIdx.x;
    const int vb0  = blockIdx.x * (BLK * JOBS);
    const int b0   = vb0 + lane;

    // Preload all 4 jobs' initial states.
    float x  = sx[b0],      y  = sy[b0];
    float yaw = syaw[b0],   sp = ssp[b0];
    const float x1 = sx[b0+32], y1 = sy[b0+32], w1 = syaw[b0+32], s1 = ssp[b0+32];
    const float x2 = sx[b0+64], y2 = sy[b0+64], w2 = syaw[b0+64], s2 = ssp[b0+64];
    const float x3 = sx[b0+96], y3 = sy[b0+96], w3 = syaw[b0+96], s3 = ssp[b0+96];

    const uint32_t mb0u = s2u(&mb[0]);
    const uint32_t cAu  = s2u(cA);
    const uint32_t cSu  = s2u(cS);
    const uint32_t sTu  = s2u(sT);

    // SW64 (ctrl): f4 col = q ^ (((base>>7) + (v>>1)) & 3)
    const int sw64 = (int)(((cAu >> 7) + (lane >> 1)) & 3);
    // SW128 (state): f4 col = col ^ (((base>>7) + v) & 7)
    const int sw128 = (int)(((sTu >> 7) + lane) & 7);

    if (lane == 0) {
        asm volatile("mbarrier.init.shared.b64 [%0], 1;" :: "r"(mb0u)     : "memory");
        asm volatile("mbarrier.init.shared.b64 [%0], 1;" :: "r"(mb0u + 8) : "memory");
        asm volatile("fence.proxy.async.shared::cta;" ::: "memory");
    }
    __syncwarp();

    // chunk g in [0,64): job = g>>4, tcoord = (g&15)*16, vcoord = vb0+(g>>4)*32,
    // ctrl buffer = g&1, mbar phase = (g>>1)&1.
#define ISSUE_LOAD(gg) do {                                                   \
        uint32_t mbar = mb0u + ((gg) & 1) * 8;                                \
        uint32_t da = cAu + ((gg) & 1) * (CT4 * 16);                          \
        uint32_t ds = cSu + ((gg) & 1) * (CT4 * 16);                          \
        int vcoord = vb0 + (((gg) >> 4) << 5);                                \
        int tcoord = ((gg) & 15) * 16;                                        \
        asm volatile("mbarrier.arrive.expect_tx.shared.b64 _, [%0], %1;"      \
                     :: "r"(mbar), "r"(4096u) : "memory");                    \
        asm volatile("cp.async.bulk.tensor.2d.shared::cta.global.tile"        \
                     ".mbarrier::complete_tx::bytes [%0], [%1, {%2, %3}], [%4];" \
                     :: "r"(da), "l"(&ta), "r"(tcoord), "r"(vcoord), "r"(mbar) \
                     : "memory");                                             \
        asm volatile("cp.async.bulk.tensor.2d.shared::cta.global.tile"        \
                     ".mbarrier::complete_tx::bytes [%0], [%1, {%2, %3}], [%4];" \
                     :: "r"(ds), "l"(&ts), "r"(tcoord), "r"(vcoord), "r"(mbar) \
                     : "memory");                                             \
    } while (0)

    if (lane == 0) { ISSUE_LOAD(0); ISSUE_LOAD(1); }

#define STEP(A, ST) do {                                                     \
        float fr   = fmaf(0.01f * sp, sp, 0.1f * sp);                        \
        float spn  = fminf(fmaxf(fmaf(DT, (A) - fr, sp), 0.0f), MAX_SPEED);  \
        float sc   = fminf(fmaxf((ST), -MAX_STEER), MAX_STEER);              \
        float angv = sp * __tanf(sc) * INV_WB;                               \
        float sn, cc2;                                                       \
        __sincosf(yaw, &sn, &cc2);                                           \
        x   = fmaf(sp * cc2, DT, x);                                         \
        y   = fmaf(sp * sn, DT, y);                                          \
        yaw = fmaf(angv, DT, yaw);                                           \
        sp  = spn;                                                           \
    } while (0)

    for (int g = 0; g < NCH; ++g) {
        const int cbuf = g & 1;
        const int cph  = (g >> 1) & 1;
        const int sbuf = (g >> 1) & 1;          // state buffer (per 2 chunks)
        const int half = g & 1;                 // which 16t half of the tile

        // Job switches (every 16 chunks).
        if (g == 16) { x = x1; y = y1; yaw = w1; sp = s1; }
        if (g == 32) { x = x2; y = y2; yaw = w2; sp = s2; }
        if (g == 48) { x = x3; y = y3; yaw = w3; sp = s3; }

        // Wait for this chunk's control tiles (acquire).
        {
            uint32_t mbar = mb0u + cbuf * 8;
            uint32_t done;
            asm volatile("{\n\t.reg .pred p;\n\t"
                         "mbarrier.try_wait.parity.acquire.cta.shared::cta.b64 p, [%1], %2;\n\t"
                         "selp.b32 %0, 1, 0, p;\n\t}"
                         : "=r"(done) : "r"(mbar), "r"(cph) : "memory");
            if (!done) {
                asm volatile("{\n\t.reg .pred P1;\n\t"
                             "W%=:\n\t"
                             "mbarrier.try_wait.parity.acquire.cta.shared::cta.b64 P1, [%0], %1, 0x989680;\n\t"
                             "@P1 bra.uni D%=;\n\t"
                             "bra.uni W%=;\n\t"
                             "D%=:\n\t}"
                             :: "r"(mbar), "r"(cph) : "memory");
            }
        }

        // Entering a fresh state buffer (even g): the store from 2 store-
        // phases ago (4 chunks back) must be done reading smem; tolerate one
        // outstanding group (previous store) -> full overlap.
        if (half == 0 && g >= 4) {
            if (lane == 0)
                asm volatile("cp.async.bulk.wait_group.read 1;" ::: "memory");
            __syncwarp();
        }

        const float4* A4p = cA + cbuf * CT4;
        const float4* S4p = cS + cbuf * CT4;
        float4* P = sT + sbuf * SB4;

#pragma unroll
        for (int q = 0; q < 4; ++q) {
            const int ci = lane * 4 + (q ^ sw64);
            float4 A4 = A4p[ci];
            float4 S4 = S4p[ci];
            float4 X, Y, W, S;
            X.x = x; Y.x = y; W.x = yaw; S.x = sp;  STEP(A4.x, S4.x);
            X.y = x; Y.y = y; W.y = yaw; S.y = sp;  STEP(A4.y, S4.y);
            X.z = x; Y.z = y; W.z = yaw; S.z = sp;  STEP(A4.z, S4.z);
            X.w = x; Y.w = y; W.w = yaw; S.w = sp;  STEP(A4.w, S4.w);
            // SW128 tile: row = v (128B), f4 col = (half*4+q) ^ phase(v)
            const int si = lane * 8 + ((half * 4 + q) ^ sw128);
            P[si]       = X;            // plane 0: x
            P[256 + si] = Y;            // plane 1: y
            P[512 + si] = W;            // plane 2: yaw
            P[768 + si] = S;            // plane 3: speed
        }
        __syncwarp();

        if (lane == 0) {
            // Store once per 2 chunks: full 128B rows, all 4 planes.
            if (half == 1) {
                asm volatile("fence.proxy.async.shared::cta;" ::: "memory");
                uint32_t src = sTu + sbuf * (SB4 * 16);
                int vcoord = vb0 + ((g >> 4) << 5);
                int tcoord = ((g >> 1) & 7) * 32;
                asm volatile("cp.async.bulk.tensor.3d.global.shared::cta.tile.bulk_group"
                             " [%0, {%1, %2, %3}], [%4];"
                             :: "l"(&to), "r"(tcoord), "r"(vcoord), "r"(0), "r"(src)
                             : "memory");
                asm volatile("cp.async.bulk.commit_group;" ::: "memory");
            }
            if (g + 2 < NCH) ISSUE_LOAD(g + 2);
        }
        __syncwarp();
    }

    if (lane == 0)
        asm volatile("cp.async.bulk.wait_group 0;" ::: "memory");
#undef STEP
#undef ISSUE_LOAD
}

// ---------------- host ----------------

typedef CUresult (*EncodeFn)(CUtensorMap*, CUtensorMapDataType, cuuint32_t, void*,
                             const cuuint64_t*, const cuuint64_t*,
                             const cuuint32_t*, const cuuint32_t*,
                             CUtensorMapInterleave, CUtensorMapSwizzle,
                             CUtensorMapL2promotion, CUtensorMapFloatOOBfill);

extern "C" void kernel_launch(void* const* d_in, const int* in_sizes, int n_in,
                              void* d_out, int out_size)
{
    (void)in_sizes; (void)n_in; (void)out_size;

    void* fptr = nullptr;
    cudaDriverEntryPointQueryResult qr;
    cudaGetDriverEntryPointByVersion("cuTensorMapEncodeTiled", &fptr, 12000,
                                     cudaEnableDefault, &qr);
    EncodeFn encode = (EncodeFn)fptr;

    CUtensorMap ta, ts, to;

    // controls: [B, 256] f32, tile 16x32, SW64 (64B rows)
    {
        cuuint64_t dims[2]    = {NS, BV};
        cuuint64_t strides[1] = {NS * 4};
        cuuint32_t box[2]     = {16, 32};
        cuuint32_t es[2]      = {1, 1};
        encode(&ta, CU_TENSOR_MAP_DATA_TYPE_FLOAT32, 2, d_in[4], dims, strides,
               box, es, CU_TENSOR_MAP_INTERLEAVE_NONE, CU_TENSOR_MAP_SWIZZLE_64B,
               CU_TENSOR_MAP_L2_PROMOTION_L2_128B, CU_TENSOR_MAP_FLOAT_OOB_FILL_NONE);
        encode(&ts, CU_TENSOR_MAP_DATA_TYPE_FLOAT32, 2, d_in[5], dims, strides,
               box, es, CU_TENSOR_MAP_INTERLEAVE_NONE, CU_TENSOR_MAP_SWIZZLE_64B,
               CU_TENSOR_MAP_L2_PROMOTION_L2_128B, CU_TENSOR_MAP_FLOAT_OOB_FILL_NONE);
    }
    // output: [4, B, 256] f32, tile 32x32x4, SW128 (full 128B rows)
    {
        cuuint64_t dims[3]    = {NS, BV, 4};
        cuuint64_t strides[2] = {NS * 4, (cuuint64_t)BV * NS * 4};
        cuuint32_t box[3]     = {32, 32, 4};
        cuuint32_t es[3]      = {1, 1, 1};
        encode(&to, CU_TENSOR_MAP_DATA_TYPE_FLOAT32, 3, d_out, dims, strides,
               box, es, CU_TENSOR_MAP_INTERLEAVE_NONE, CU_TENSOR_MAP_SWIZZLE_128B,
               CU_TENSOR_MAP_L2_PROMOTION_L2_128B, CU_TENSOR_MAP_FLOAT_OOB_FILL_NONE);
    }

    bicycle_kernel<<<BV / (BLK * JOBS), BLK>>>(
        ta, ts, to,
        (const float*)d_in[0], (const float*)d_in[1],
        (const float*)d_in[2], (const float*)d_in[3]);
}

// round 15
// speedup vs baseline: 1.2388x; 1.2388x over previous
#include <cuda_runtime.h>
#include <cuda.h>
#include <cstdint>

// BicycleModel: B=65536 vehicles, 256 steps, 4 output planes [B,256] f32.
// R15: 2 warps/block share TMA traffic — half the TMA requests, double size.
//  - BLK=64 (1 vehicle/thread), TC=16 chunks
//  - controls: ONE TMA 2D load {16,64} per array per chunk (SW64), 2 bufs,
//    prefetch distance 2
//  - states: ONE 3D TMA store {16,64,4} per chunk (SW64), 2 bufs,
//    wait_group.read 1
//  - smem 48KB+pad dynamic -> 4 blocks/SM -> 8 warps/SM (most yet with full
//    double buffering); grid 1024, 1.73 waves (waves shown to be non-factor)

constexpr int BV  = 65536;
constexpr int NS  = 256;
constexpr int BLK = 64;            // 2 warps, 64 vehicles per block
constexpr int NCH = 16;            // chunks of 16 timesteps
constexpr int CT4 = 256;           // float4 per 64v x 16t ctrl tile (4KB)
constexpr int SB4 = 1024;          // float4 per state buffer (4p x 64v x 4)

constexpr float DT        = 0.05f;
constexpr float MAX_STEER = 0.52359877559829887f;
constexpr float MAX_SPEED = 100.0f;
constexpr float INV_WB    = 1.0f / 2.7f;

constexpr int SMEM_BYTES = 1024 + (2 * CT4 + 2 * CT4 + 2 * SB4) * 16; // 50176

__device__ __forceinline__ uint32_t s2u(const void* p) {
    uint32_t a;
    asm("{ .reg .u64 t; cvta.to.shared.u64 t, %1; cvt.u32.u64 %0, t; }"
        : "=r"(a) : "l"(p));
    return a;
}

__global__ __launch_bounds__(BLK)
void bicycle_kernel(const __grid_constant__ CUtensorMap ta,   // acc  [B,256]
                    const __grid_constant__ CUtensorMap ts,   // steer[B,256]
                    const __grid_constant__ CUtensorMap to,   // out  [4,B,256]
                    const float* __restrict__ sx,
                    const float* __restrict__ sy,
                    const float* __restrict__ syaw,
                    const float* __restrict__ ssp)
{
    extern __shared__ char smem_raw[];
    __shared__ alignas(8) unsigned long long mb[2];

    // 1024-align the pool so swizzle phases are uniform (bits 0-6 zero and
    // all sub-buffers at 2KB multiples).
    char* base = (char*)(((uintptr_t)smem_raw + 1023) & ~(uintptr_t)1023);
    float4* cA = (float4*)base;          // [2][256] accel tiles (4KB each)
    float4* cS = cA + 2 * CT4;           // [2][256] steer tiles
    float4* sT = cS + 2 * CT4;           // [2][1024] state bufs (16KB each)

    const int tid = threadIdx.x;
    const int vb  = blockIdx.x * BLK;
    const int b   = vb + tid;

    float x   = sx[b];
    float y   = sy[b];
    float yaw = syaw[b];
    float sp  = ssp[b];

    const uint32_t mb0u = s2u(&mb[0]);
    const uint32_t cAu  = s2u(cA);
    const uint32_t cSu  = s2u(cS);
    const uint32_t sTu  = s2u(sT);

    // SW64 swizzle: f4 column = q ^ (((base>>7) + (v>>1)) & 3).
    const int swc = (int)(((cAu >> 7) + (tid >> 1)) & 3);
    const int sws = (int)(((sTu >> 7) + (tid >> 1)) & 3);

    if (tid == 0) {
        asm volatile("mbarrier.init.shared.b64 [%0], 1;" :: "r"(mb0u)     : "memory");
        asm volatile("mbarrier.init.shared.b64 [%0], 1;" :: "r"(mb0u + 8) : "memory");
        asm volatile("fence.proxy.async.shared::cta;" ::: "memory");
    }
    __syncthreads();

    // One {16,64} load per array per chunk: 4096B each, 8192B per mbarrier.
#define ISSUE_LOAD(cc) do {                                                   \
        uint32_t mbar = mb0u + ((cc) & 1) * 8;                                \
        uint32_t da = cAu + ((cc) & 1) * (CT4 * 16);                          \
        uint32_t ds = cSu + ((cc) & 1) * (CT4 * 16);                          \
        asm volatile("mbarrier.arrive.expect_tx.shared.b64 _, [%0], %1;"      \
                     :: "r"(mbar), "r"(8192u) : "memory");                    \
        asm volatile("cp.async.bulk.tensor.2d.shared::cta.global.tile"        \
                     ".mbarrier::complete_tx::bytes [%0], [%1, {%2, %3}], [%4];" \
                     :: "r"(da), "l"(&ta), "r"((cc) * 16), "r"(vb), "r"(mbar) \
                     : "memory");                                             \
        asm volatile("cp.async.bulk.tensor.2d.shared::cta.global.tile"        \
                     ".mbarrier::complete_tx::bytes [%0], [%1, {%2, %3}], [%4];" \
                     :: "r"(ds), "l"(&ts), "r"((cc) * 16), "r"(vb), "r"(mbar) \
                     : "memory");                                             \
    } while (0)

    if (tid == 0) { ISSUE_LOAD(0); ISSUE_LOAD(1); }

#define STEP(A, ST) do {                                                     \
        float fr   = fmaf(0.01f * sp, sp, 0.1f * sp);                        \
        float spn  = fminf(fmaxf(fmaf(DT, (A) - fr, sp), 0.0f), MAX_SPEED);  \
        float sc   = fminf(fmaxf((ST), -MAX_STEER), MAX_STEER);              \
        float angv = sp * __tanf(sc) * INV_WB;                               \
        float sn, cc2;                                                       \
        __sincosf(yaw, &sn, &cc2);                                           \
        x   = fmaf(sp * cc2, DT, x);                                         \
        y   = fmaf(sp * sn, DT, y);                                          \
        yaw = fmaf(angv, DT, yaw);                                           \
        sp  = spn;                                                           \
    } while (0)

    for (int c = 0; c < NCH; ++c) {
        const int buf = c & 1;
        const int ph  = (c >> 1) & 1;

        // Wait for this chunk's control tiles (acquire) — all threads poll.
        {
            uint32_t mbar = mb0u + buf * 8;
            uint32_t done;
            asm volatile("{\n\t.reg .pred p;\n\t"
                         "mbarrier.try_wait.parity.acquire.cta.shared::cta.b64 p, [%1], %2;\n\t"
                         "selp.b32 %0, 1, 0, p;\n\t}"
                         : "=r"(done) : "r"(mbar), "r"(ph) : "memory");
            if (!done) {
                asm volatile("{\n\t.reg .pred P1;\n\t"
                             "W%=:\n\t"
                             "mbarrier.try_wait.parity.acquire.cta.shared::cta.b64 P1, [%0], %1, 0x989680;\n\t"
                             "@P1 bra.uni D%=;\n\t"
                             "bra.uni W%=;\n\t"
                             "D%=:\n\t}"
                             :: "r"(mbar), "r"(ph) : "memory");
            }
        }

        // State buffer reuse: store from chunk c-2 (same buffer) must be done
        // reading smem; tolerate one outstanding group (c-1) -> overlap.
        if (c >= 2) {
            if (tid == 0)
                asm volatile("cp.async.bulk.wait_group.read 1;" ::: "memory");
            __syncthreads();
        }

        const float4* A4p = cA + buf * CT4;
        const float4* S4p = cS + buf * CT4;
        float4* P = sT + buf * SB4;

#pragma unroll
        for (int q = 0; q < 4; ++q) {
            const int ci = tid * 4 + (q ^ swc);
            float4 A4 = A4p[ci];
            float4 S4 = S4p[ci];
            float4 X, Y, W, S;
            X.x = x; Y.x = y; W.x = yaw; S.x = sp;  STEP(A4.x, S4.x);
            X.y = x; Y.y = y; W.y = yaw; S.y = sp;  STEP(A4.y, S4.y);
            X.z = x; Y.z = y; W.z = yaw; S.z = sp;  STEP(A4.z, S4.z);
            X.w = x; Y.w = y; W.w = yaw; S.w = sp;  STEP(A4.w, S4.w);
            const int si = tid * 4 + (q ^ sws);
            P[si]       = X;            // plane 0: x
            P[256 + si] = Y;            // plane 1: y
            P[512 + si] = W;            // plane 2: yaw
            P[768 + si] = S;            // plane 3: speed
        }
        __syncthreads();    // both warps' STS done before thread 0 stores

        // ONE 3D TMA store {16,64,4}; then prefetch controls c+2.
        if (tid == 0) {
            asm volatile("fence.proxy.async.shared::cta;" ::: "memory");
            uint32_t src = sTu + buf * (SB4 * 16);
            asm volatile("cp.async.bulk.tensor.3d.global.shared::cta.tile.bulk_group"
                         " [%0, {%1, %2, %3}], [%4];"
                         :: "l"(&to), "r"(c * 16), "r"(vb), "r"(0), "r"(src)
                         : "memory");
            asm volatile("cp.async.bulk.commit_group;" ::: "memory");
            if (c + 2 < NCH) ISSUE_LOAD(c + 2);
        }
        __syncthreads();
    }

    if (tid == 0)
        asm volatile("cp.async.bulk.wait_group 0;" ::: "memory");
#undef STEP
#undef ISSUE_LOAD
}

// ---------------- host ----------------

typedef CUresult (*EncodeFn)(CUtensorMap*, CUtensorMapDataType, cuuint32_t, void*,
                             const cuuint64_t*, const cuuint64_t*,
                             const cuuint32_t*, const cuuint32_t*,
                             CUtensorMapInterleave, CUtensorMapSwizzle,
                             CUtensorMapL2promotion, CUtensorMapFloatOOBfill);

extern "C" void kernel_launch(void* const* d_in, const int* in_sizes, int n_in,
                              void* d_out, int out_size)
{
    (void)in_sizes; (void)n_in; (void)out_size;

    void* fptr = nullptr;
    cudaDriverEntryPointQueryResult qr;
    cudaGetDriverEntryPointByVersion("cuTensorMapEncodeTiled", &fptr, 12000,
                                     cudaEnableDefault, &qr);
    EncodeFn encode = (EncodeFn)fptr;

    CUtensorMap ta, ts, to;

    // controls: [B, 256] f32, tile 16x64, SW64 (64B rows)
    {
        cuuint64_t dims[2]    = {NS, BV};
        cuuint64_t strides[1] = {NS * 4};
        cuuint32_t box[2]     = {16, 64};
        cuuint32_t es[2]      = {1, 1};
        encode(&ta, CU_TENSOR_MAP_DATA_TYPE_FLOAT32, 2, d_in[4], dims, strides,
               box, es, CU_TENSOR_MAP_INTERLEAVE_NONE, CU_TENSOR_MAP_SWIZZLE_64B,
               CU_TENSOR_MAP_L2_PROMOTION_L2_128B, CU_TENSOR_MAP_FLOAT_OOB_FILL_NONE);
        encode(&ts, CU_TENSOR_MAP_DATA_TYPE_FLOAT32, 2, d_in[5], dims, strides,
               box, es, CU_TENSOR_MAP_INTERLEAVE_NONE, CU_TENSOR_MAP_SWIZZLE_64B,
               CU_TENSOR_MAP_L2_PROMOTION_L2_128B, CU_TENSOR_MAP_FLOAT_OOB_FILL_NONE);
    }
    // output: [4, B, 256] f32, tile 16x64x4, SW64
    {
        cuuint64_t dims[3]    = {NS, BV, 4};
        cuuint64_t strides[2] = {NS * 4, (cuuint64_t)BV * NS * 4};
        cuuint32_t box[3]     = {16, 64, 4};
        cuuint32_t es[3]      = {1, 1, 1};
        encode(&to, CU_TENSOR_MAP_DATA_TYPE_FLOAT32, 3, d_out, dims, strides,
               box, es, CU_TENSOR_MAP_INTERLEAVE_NONE, CU_TENSOR_MAP_SWIZZLE_64B,
               CU_TENSOR_MAP_L2_PROMOTION_L2_128B, CU_TENSOR_MAP_FLOAT_OOB_FILL_NONE);
    }

    cudaFuncSetAttribute(bicycle_kernel,
                         cudaFuncAttributeMaxDynamicSharedMemorySize, SMEM_BYTES);

    bicycle_kernel<<<BV / BLK, BLK, SMEM_BYTES>>>(
        ta, ts, to,
        (const float*)d_in[0], (const float*)d_in[1],
        (const float*)d_in[2], (const float*)d_in[3]);
}